// round 5
// baseline (speedup 1.0000x reference)
#include <cuda_runtime.h>
#include <cuda_fp16.h>

// Problem constants
#define HOPS  3
#define VOCAB 50257
#define EMB   128
#define MEM   256   // memory slots (M)
#define BATCH 16    // batch (B)
#define SENT  64    // sentence length (S)

// fp16 copies of tables C1..C3 (C0 is never needed: hop-0 softmax of zero
// logits is exactly uniform). 3 * 50257 * 128 * 2B = 38.6 MB static scratch.
__device__ __align__(16) __half g_Ch[3ULL * VOCAB * EMB];

// E[t][b][m][d] = sum_s C[t+1][story[m][b][s]][d], stored fp16 (3.1 MB).
__device__ __align__(16) __half g_Eh[3][BATCH][MEM][EMB];

// ---------------------------------------------------------------------------
// Kernel 0: fp32 -> fp16 conversion of tables C1..C3.
// 8 elements per thread: 2x LDG.128 in, 1x STG.128 out.
// ---------------------------------------------------------------------------
__global__ void __launch_bounds__(256) convert_kernel(const float* __restrict__ C) {
    const size_t N8 = (3ULL * VOCAB * EMB) / 8;           // 2,412,336
    size_t i = (size_t)blockIdx.x * blockDim.x + threadIdx.x;
    if (i >= N8) return;

    const float4* __restrict__ src = (const float4*)(C + (size_t)VOCAB * EMB);
    float4 a = __ldg(src + 2 * i);
    float4 b = __ldg(src + 2 * i + 1);

    __half2 h0 = __floats2half2_rn(a.x, a.y);
    __half2 h1 = __floats2half2_rn(a.z, a.w);
    __half2 h2 = __floats2half2_rn(b.x, b.y);
    __half2 h3 = __floats2half2_rn(b.z, b.w);

    uint4 o;
    o.x = *reinterpret_cast<unsigned int*>(&h0);
    o.y = *reinterpret_cast<unsigned int*>(&h1);
    o.z = *reinterpret_cast<unsigned int*>(&h2);
    o.w = *reinterpret_cast<unsigned int*>(&h3);
    ((uint4*)g_Ch)[i] = o;
}

// ---------------------------------------------------------------------------
// Kernel A: gather-sum embeddings from fp16 tables. One WARP per (t, b, m).
// Row = 256B: 32 lanes x 8B (uint2 = 4 halves). fp32 accumulation.
// ---------------------------------------------------------------------------
__global__ void __launch_bounds__(128) gather_kernel(const int* __restrict__ story) {
    const int warps_per_block = blockDim.x >> 5;
    const int gw   = blockIdx.x * warps_per_block + (threadIdx.x >> 5);
    const int lane = threadIdx.x & 31;

    const int t   = gw / (BATCH * MEM);
    const int rem = gw % (BATCH * MEM);
    const int b   = rem / MEM;
    const int m   = rem % MEM;

    // story layout: (MEM, BATCH, SENT) row-major
    const int* toks = story + ((size_t)m * BATCH + b) * SENT;
    const int tok_lo = toks[lane];
    const int tok_hi = toks[lane + 32];

    // table t: rows of 32 uint2 (128 halves)
    const uint2* __restrict__ tab =
        (const uint2*)g_Ch + (size_t)t * VOCAB * (EMB / 4);

    float4 a0 = make_float4(0.f, 0.f, 0.f, 0.f);
    float4 a1 = make_float4(0.f, 0.f, 0.f, 0.f);

#pragma unroll
    for (int s = 0; s < 32; s++) {
        int tok = __shfl_sync(0xffffffffu, tok_lo, s);
        uint2 v = __ldg(tab + (size_t)tok * 32 + lane);
        float2 f0 = __half22float2(*reinterpret_cast<__half2*>(&v.x));
        float2 f1 = __half22float2(*reinterpret_cast<__half2*>(&v.y));
        a0.x += f0.x; a0.y += f0.y; a0.z += f1.x; a0.w += f1.y;
    }
#pragma unroll
    for (int s = 0; s < 32; s++) {
        int tok = __shfl_sync(0xffffffffu, tok_hi, s);
        uint2 v = __ldg(tab + (size_t)tok * 32 + lane);
        float2 f0 = __half22float2(*reinterpret_cast<__half2*>(&v.x));
        float2 f1 = __half22float2(*reinterpret_cast<__half2*>(&v.y));
        a1.x += f0.x; a1.y += f0.y; a1.z += f1.x; a1.w += f1.y;
    }

    __half2 o0 = __floats2half2_rn(a0.x + a1.x, a0.y + a1.y);
    __half2 o1 = __floats2half2_rn(a0.z + a1.z, a0.w + a1.w);
    uint2 o;
    o.x = *reinterpret_cast<unsigned int*>(&o0);
    o.y = *reinterpret_cast<unsigned int*>(&o1);
    ((uint2*)g_Eh[t][b][m])[lane] = o;
}

// ---------------------------------------------------------------------------
// Kernel B: hop loop. One block of 1024 threads per batch element.
// E rows are fp16; all accumulation in fp32.
// ---------------------------------------------------------------------------
__global__ void __launch_bounds__(1024) hops_kernel(float* __restrict__ out) {
    __shared__ float4 part[32][32];   // per-warp partial float4s (16 KB)
    __shared__ float  prob[MEM];
    __shared__ float4 us[32];         // state u as 32 float4s (fp32)
    __shared__ float  red[8];

    const int b    = blockIdx.x;
    const int tid  = threadIdx.x;
    const int w    = tid >> 5;        // warp 0..31
    const int lane = tid & 31;

    // ---------- hop 0: u = mean_m E0[b][m]  (uniform softmax, exact) ----------
    {
        const uint2* __restrict__ E0 = (const uint2*)g_Eh[0][b];
        float4 acc = make_float4(0.f, 0.f, 0.f, 0.f);
#pragma unroll
        for (int k = 0; k < 8; k++) {
            uint2 v = E0[(size_t)(w * 8 + k) * 32 + lane];
            float2 f0 = __half22float2(*reinterpret_cast<__half2*>(&v.x));
            float2 f1 = __half22float2(*reinterpret_cast<__half2*>(&v.y));
            acc.x += f0.x; acc.y += f0.y; acc.z += f1.x; acc.w += f1.y;
        }
        part[w][lane] = acc;
        __syncthreads();
#pragma unroll
        for (int off = 16; off >= 1; off >>= 1) {
            if (w < off) {
                float4 a = part[w][lane], c = part[w + off][lane];
                a.x += c.x; a.y += c.y; a.z += c.z; a.w += c.w;
                part[w][lane] = a;
            }
            __syncthreads();
        }
        if (tid < 32) {
            float4 a = part[0][tid];
            a.x *= (1.f / MEM); a.y *= (1.f / MEM); a.z *= (1.f / MEM); a.w *= (1.f / MEM);
            us[tid] = a;
        }
        __syncthreads();
    }

    // ---------- hops 1 and 2 ----------
    for (int h = 1; h <= 2; h++) {
        // --- logits[m] = dot(E[h-1][b][m], u). 4 lanes per slot, 8 loads each. ---
        {
            const uint2* __restrict__ Ep = (const uint2*)g_Eh[h - 1][b];
            const int q = lane & 3;           // quarter-of-quarter: 4 dims per load
            const int m = w * 8 + (lane >> 2);
            float pd = 0.f;
#pragma unroll
            for (int j = 0; j < 8; j++) {
                uint2 v = Ep[(size_t)m * 32 + q + j * 4];
                float2 f0 = __half22float2(*reinterpret_cast<__half2*>(&v.x));
                float2 f1 = __half22float2(*reinterpret_cast<__half2*>(&v.y));
                float4 uu = us[q + j * 4];
                pd += f0.x * uu.x + f0.y * uu.y + f1.x * uu.z + f1.y * uu.w;
            }
            pd += __shfl_xor_sync(0xffffffffu, pd, 1);
            pd += __shfl_xor_sync(0xffffffffu, pd, 2);
            if (q == 0) prob[m] = pd;
            __syncthreads();
        }

        // --- softmax over prob[0..255] ---
        {
            float x = (tid < MEM) ? prob[tid] : -1e30f;
            float mx = x;
#pragma unroll
            for (int off = 16; off; off >>= 1)
                mx = fmaxf(mx, __shfl_xor_sync(0xffffffffu, mx, off));
            if (lane == 0 && w < 8) red[w] = mx;
            __syncthreads();
            mx = red[0];
#pragma unroll
            for (int i = 1; i < 8; i++) mx = fmaxf(mx, red[i]);
            __syncthreads();            // all reads of red done before rewrite

            float ev = (tid < MEM) ? __expf(x - mx) : 0.f;
            float sv = ev;
#pragma unroll
            for (int off = 16; off; off >>= 1)
                sv += __shfl_xor_sync(0xffffffffu, sv, off);
            if (lane == 0 && w < 8) red[w] = sv;
            __syncthreads();
            float tot = red[0];
#pragma unroll
            for (int i = 1; i < 8; i++) tot += red[i];

            if (tid < MEM) prob[tid] = ev / tot;
            __syncthreads();
        }

        // --- o[d] = sum_m prob[m] * E[h][b][m][d]; u += o ---
        {
            const uint2* __restrict__ Ec = (const uint2*)g_Eh[h][b];
            float4 acc = make_float4(0.f, 0.f, 0.f, 0.f);
#pragma unroll
            for (int k = 0; k < 8; k++) {
                const int mm = w * 8 + k;
                float p = prob[mm];
                uint2 v = Ec[(size_t)mm * 32 + lane];
                float2 f0 = __half22float2(*reinterpret_cast<__half2*>(&v.x));
                float2 f1 = __half22float2(*reinterpret_cast<__half2*>(&v.y));
                acc.x += p * f0.x; acc.y += p * f0.y; acc.z += p * f1.x; acc.w += p * f1.y;
            }
            part[w][lane] = acc;
            __syncthreads();
#pragma unroll
            for (int off = 16; off >= 1; off >>= 1) {
                if (w < off) {
                    float4 a = part[w][lane], c = part[w + off][lane];
                    a.x += c.x; a.y += c.y; a.z += c.z; a.w += c.w;
                    part[w][lane] = a;
                }
                __syncthreads();
            }
            if (tid < 32) {
                float4 a = us[tid], c = part[0][tid];
                a.x += c.x; a.y += c.y; a.z += c.z; a.w += c.w;
                us[tid] = a;
            }
            __syncthreads();
        }
    }

    // write out[b] (128 floats = 32 float4)
    if (tid < 32)
        ((float4*)out)[(size_t)b * 32 + tid] = us[tid];
}

extern "C" void kernel_launch(void* const* d_in, const int* in_sizes, int n_in,
                              void* d_out, int out_size) {
    const int*   story = (const int*)d_in[0];   // (256, 16, 64) int32
    const float* C     = (const float*)d_in[1]; // (4, 50257, 128) fp32
    float*       out   = (float*)d_out;         // (16, 128) fp32

    (void)in_sizes; (void)n_in; (void)out_size;

    const size_t N8 = (3ULL * VOCAB * EMB) / 8;
    const int conv_blocks = (int)((N8 + 255) / 256);  // 9424
    convert_kernel<<<conv_blocks, 256>>>(C);

    const int total_warps = 3 * BATCH * MEM;          // 12288
    const int blocks = total_warps / 4;               // 3072
    gather_kernel<<<blocks, 128>>>(story);

    hops_kernel<<<BATCH, 1024>>>(out);
}

// round 6
// speedup vs baseline: 1.0537x; 1.0537x over previous
#include <cuda_runtime.h>
#include <cuda_fp16.h>

// Problem constants
#define HOPS  3
#define VOCAB 50257
#define EMB   128
#define MEM   256   // memory slots (M)
#define BATCH 16    // batch (B)
#define SENT  64    // sentence length (S)

#define TBL_ELEMS   ((size_t)VOCAB * EMB)          // elements per table
#define TBL_ITEMS8  (TBL_ELEMS / 8)                // uint4 items per table (804112)

// fp16 copies of tables C1..C3 (C0 never needed: hop-0 softmax of zero logits
// is exactly uniform). 3 * 50257 * 128 * 2B = 38.6 MB static scratch.
__device__ __align__(16) __half g_Ch[3ULL * VOCAB * EMB];

// E[t][b][m][d] = sum_s C[t+1][story[m][b][s]][d], stored fp16 (3.1 MB).
__device__ __align__(16) __half g_Eh[3][BATCH][MEM][EMB];

// ---------------------------------------------------------------------------
// Device helpers
// ---------------------------------------------------------------------------
// Convert one uint4-item (8 floats -> 8 halves) of table `tbl` (0..2 -> C1..C3).
__device__ __forceinline__ void convert_item(const float* __restrict__ C,
                                             int tbl, size_t i) {
    const float4* __restrict__ src =
        (const float4*)(C + (size_t)(tbl + 1) * TBL_ELEMS);
    float4 a = __ldg(src + 2 * i);
    float4 b = __ldg(src + 2 * i + 1);

    __half2 h0 = __floats2half2_rn(a.x, a.y);
    __half2 h1 = __floats2half2_rn(a.z, a.w);
    __half2 h2 = __floats2half2_rn(b.x, b.y);
    __half2 h3 = __floats2half2_rn(b.z, b.w);

    uint4 o;
    o.x = *reinterpret_cast<unsigned int*>(&h0);
    o.y = *reinterpret_cast<unsigned int*>(&h1);
    o.z = *reinterpret_cast<unsigned int*>(&h2);
    o.w = *reinterpret_cast<unsigned int*>(&h3);
    ((uint4*)g_Ch)[(size_t)tbl * TBL_ITEMS8 + i] = o;
}

// Gather-sum one (t, b, m) unit with one warp, from fp16 table t.
__device__ __forceinline__ void gather_unit(const int* __restrict__ story,
                                            int t, int b, int m, int lane) {
    const int* toks = story + ((size_t)m * BATCH + b) * SENT;
    const int tok_lo = toks[lane];
    const int tok_hi = toks[lane + 32];

    const uint2* __restrict__ tab =
        (const uint2*)g_Ch + (size_t)t * VOCAB * (EMB / 4);

    float4 a0 = make_float4(0.f, 0.f, 0.f, 0.f);
    float4 a1 = make_float4(0.f, 0.f, 0.f, 0.f);

#pragma unroll
    for (int s = 0; s < 32; s++) {
        int tok = __shfl_sync(0xffffffffu, tok_lo, s);
        uint2 v = __ldg(tab + (size_t)tok * 32 + lane);
        float2 f0 = __half22float2(*reinterpret_cast<__half2*>(&v.x));
        float2 f1 = __half22float2(*reinterpret_cast<__half2*>(&v.y));
        a0.x += f0.x; a0.y += f0.y; a0.z += f1.x; a0.w += f1.y;
    }
#pragma unroll
    for (int s = 0; s < 32; s++) {
        int tok = __shfl_sync(0xffffffffu, tok_hi, s);
        uint2 v = __ldg(tab + (size_t)tok * 32 + lane);
        float2 f0 = __half22float2(*reinterpret_cast<__half2*>(&v.x));
        float2 f1 = __half22float2(*reinterpret_cast<__half2*>(&v.y));
        a1.x += f0.x; a1.y += f0.y; a1.z += f1.x; a1.w += f1.y;
    }

    __half2 o0 = __floats2half2_rn(a0.x + a1.x, a0.y + a1.y);
    __half2 o1 = __floats2half2_rn(a0.z + a1.z, a0.w + a1.w);
    uint2 o;
    o.x = *reinterpret_cast<unsigned int*>(&o0);
    o.y = *reinterpret_cast<unsigned int*>(&o1);
    ((uint2*)g_Eh[t][b][m])[lane] = o;
}

// ---------------------------------------------------------------------------
// K1: convert tables C1, C2 -> g_Ch[0], g_Ch[1]. DRAM-bound (~77 MB).
// ---------------------------------------------------------------------------
__global__ void __launch_bounds__(256) conv01_kernel(const float* __restrict__ C) {
    size_t i = (size_t)blockIdx.x * blockDim.x + threadIdx.x;
    const size_t N = 2 * TBL_ITEMS8;
    if (i >= N) return;
    int tbl = (i < TBL_ITEMS8) ? 0 : 1;
    size_t j = (tbl == 0) ? i : i - TBL_ITEMS8;
    convert_item(C, tbl, j);
}

// ---------------------------------------------------------------------------
// K2 (fused): blocks [0, GB_GATHER): gather t=0 (L2-bound)
//             blocks [GB_GATHER, ...): convert table C3 (DRAM-bound)
// Independent roles -> DRAM and LTS overlap inside one launch.
// ---------------------------------------------------------------------------
#define GB_GATHER 1024   // 4 warps/block * 1024 = 4096 warps = BATCH*MEM units
#define GB_CONV   1024   // grid-stride over TBL_ITEMS8 items

__global__ void __launch_bounds__(128) fused_g0_c2_kernel(const int* __restrict__ story,
                                                          const float* __restrict__ C) {
    if (blockIdx.x < GB_GATHER) {
        const int w    = blockIdx.x * 4 + (threadIdx.x >> 5); // 0..4095
        const int lane = threadIdx.x & 31;
        const int b = w / MEM;
        const int m = w % MEM;
        gather_unit(story, 0, b, m, lane);
    } else {
        size_t i = (size_t)(blockIdx.x - GB_GATHER) * 128 + threadIdx.x;
        const size_t stride = (size_t)GB_CONV * 128;
        for (; i < TBL_ITEMS8; i += stride)
            convert_item(C, 2, i);
    }
}

// ---------------------------------------------------------------------------
// K3: gather t=1 and t=2 (pure L2, ~134 MB).
// ---------------------------------------------------------------------------
__global__ void __launch_bounds__(128) gather12_kernel(const int* __restrict__ story) {
    const int w    = blockIdx.x * 4 + (threadIdx.x >> 5);   // 0..8191
    const int lane = threadIdx.x & 31;
    const int t    = 1 + (w >> 12);        // 4096 units per table
    const int rem  = w & 4095;
    const int b = rem / MEM;
    const int m = rem % MEM;
    gather_unit(story, t, b, m, lane);
}

// ---------------------------------------------------------------------------
// K4: hop loop. One block of 1024 threads per batch element. (Unchanged.)
// ---------------------------------------------------------------------------
__global__ void __launch_bounds__(1024) hops_kernel(float* __restrict__ out) {
    __shared__ float4 part[32][32];
    __shared__ float  prob[MEM];
    __shared__ float4 us[32];
    __shared__ float  red[8];

    const int b    = blockIdx.x;
    const int tid  = threadIdx.x;
    const int w    = tid >> 5;
    const int lane = tid & 31;

    // ---------- hop 0: u = mean_m E0[b][m] (uniform softmax, exact) ----------
    {
        const uint2* __restrict__ E0 = (const uint2*)g_Eh[0][b];
        float4 acc = make_float4(0.f, 0.f, 0.f, 0.f);
#pragma unroll
        for (int k = 0; k < 8; k++) {
            uint2 v = E0[(size_t)(w * 8 + k) * 32 + lane];
            float2 f0 = __half22float2(*reinterpret_cast<__half2*>(&v.x));
            float2 f1 = __half22float2(*reinterpret_cast<__half2*>(&v.y));
            acc.x += f0.x; acc.y += f0.y; acc.z += f1.x; acc.w += f1.y;
        }
        part[w][lane] = acc;
        __syncthreads();
#pragma unroll
        for (int off = 16; off >= 1; off >>= 1) {
            if (w < off) {
                float4 a = part[w][lane], c = part[w + off][lane];
                a.x += c.x; a.y += c.y; a.z += c.z; a.w += c.w;
                part[w][lane] = a;
            }
            __syncthreads();
        }
        if (tid < 32) {
            float4 a = part[0][tid];
            a.x *= (1.f / MEM); a.y *= (1.f / MEM); a.z *= (1.f / MEM); a.w *= (1.f / MEM);
            us[tid] = a;
        }
        __syncthreads();
    }

    // ---------- hops 1 and 2 ----------
    for (int h = 1; h <= 2; h++) {
        // logits[m] = dot(E[h-1][b][m], u); 4 lanes per slot, 8 loads each
        {
            const uint2* __restrict__ Ep = (const uint2*)g_Eh[h - 1][b];
            const int q = lane & 3;
            const int m = w * 8 + (lane >> 2);
            float pd = 0.f;
#pragma unroll
            for (int j = 0; j < 8; j++) {
                uint2 v = Ep[(size_t)m * 32 + q + j * 4];
                float2 f0 = __half22float2(*reinterpret_cast<__half2*>(&v.x));
                float2 f1 = __half22float2(*reinterpret_cast<__half2*>(&v.y));
                float4 uu = us[q + j * 4];
                pd += f0.x * uu.x + f0.y * uu.y + f1.x * uu.z + f1.y * uu.w;
            }
            pd += __shfl_xor_sync(0xffffffffu, pd, 1);
            pd += __shfl_xor_sync(0xffffffffu, pd, 2);
            if (q == 0) prob[m] = pd;
            __syncthreads();
        }

        // softmax over prob[0..255]
        {
            float x = (tid < MEM) ? prob[tid] : -1e30f;
            float mx = x;
#pragma unroll
            for (int off = 16; off; off >>= 1)
                mx = fmaxf(mx, __shfl_xor_sync(0xffffffffu, mx, off));
            if (lane == 0 && w < 8) red[w] = mx;
            __syncthreads();
            mx = red[0];
#pragma unroll
            for (int i = 1; i < 8; i++) mx = fmaxf(mx, red[i]);
            __syncthreads();

            float ev = (tid < MEM) ? __expf(x - mx) : 0.f;
            float sv = ev;
#pragma unroll
            for (int off = 16; off; off >>= 1)
                sv += __shfl_xor_sync(0xffffffffu, sv, off);
            if (lane == 0 && w < 8) red[w] = sv;
            __syncthreads();
            float tot = red[0];
#pragma unroll
            for (int i = 1; i < 8; i++) tot += red[i];

            if (tid < MEM) prob[tid] = ev / tot;
            __syncthreads();
        }

        // o[d] = sum_m prob[m] * E[h][b][m][d]; u += o
        {
            const uint2* __restrict__ Ec = (const uint2*)g_Eh[h][b];
            float4 acc = make_float4(0.f, 0.f, 0.f, 0.f);
#pragma unroll
            for (int k = 0; k < 8; k++) {
                const int mm = w * 8 + k;
                float p = prob[mm];
                uint2 v = Ec[(size_t)mm * 32 + lane];
                float2 f0 = __half22float2(*reinterpret_cast<__half2*>(&v.x));
                float2 f1 = __half22float2(*reinterpret_cast<__half2*>(&v.y));
                acc.x += p * f0.x; acc.y += p * f0.y; acc.z += p * f1.x; acc.w += p * f1.y;
            }
            part[w][lane] = acc;
            __syncthreads();
#pragma unroll
            for (int off = 16; off >= 1; off >>= 1) {
                if (w < off) {
                    float4 a = part[w][lane], c = part[w + off][lane];
                    a.x += c.x; a.y += c.y; a.z += c.z; a.w += c.w;
                    part[w][lane] = a;
                }
                __syncthreads();
            }
            if (tid < 32) {
                float4 a = us[tid], c = part[0][tid];
                a.x += c.x; a.y += c.y; a.z += c.z; a.w += c.w;
                us[tid] = a;
            }
            __syncthreads();
        }
    }

    if (tid < 32)
        ((float4*)out)[(size_t)b * 32 + tid] = us[tid];
}

extern "C" void kernel_launch(void* const* d_in, const int* in_sizes, int n_in,
                              void* d_out, int out_size) {
    const int*   story = (const int*)d_in[0];   // (256, 16, 64) int32
    const float* C     = (const float*)d_in[1]; // (4, 50257, 128) fp32
    float*       out   = (float*)d_out;         // (16, 128) fp32

    (void)in_sizes; (void)n_in; (void)out_size;

    // K1: convert C1, C2 (DRAM-bound)
    const size_t n01 = 2 * TBL_ITEMS8;
    conv01_kernel<<<(int)((n01 + 255) / 256), 256>>>(C);

    // K2: gather t0 (L2) overlapped with convert C3 (DRAM)
    fused_g0_c2_kernel<<<GB_GATHER + GB_CONV, 128>>>(story, C);

    // K3: gather t1, t2 (L2)
    gather12_kernel<<<2048, 128>>>(story);

    // K4: hops
    hops_kernel<<<BATCH, 1024>>>(out);
}